// round 14
// baseline (speedup 1.0000x reference)
#include <cuda_runtime.h>
#include <math.h>

#define N_ELEMS 16384
#define NBINS   4096
#define NCTA    128
#define TPB     128
#define BPT     (NBINS / TPB)          // 32 bins per thread
#define DELTA_F 0.1f
#define EPS_F   1e-12f
#define FIX_SCALE 4294967296.0         // 2^32

// K3 dynamic smem: [0, 16400) s_pref ints, [16640, +65536) s_sorted
#define SMEM_SORT_OFF    16640          // 128B-aligned
#define SMEM_TOTAL_BYTES (SMEM_SORT_OFF + N_ELEMS * 4)

// ---- scratch (__device__ globals; zero-initialized at load) ----------------
__device__ float d_g[N_ELEMS];
__device__ float d_loss[N_ELEMS];
__device__ int   d_pack[N_ELEMS];             // (bin << 14) | rank
__device__ float d_sorted[N_ELEMS];           // contiguous bin-sorted values
__device__ int   d_hist[NBINS];               // invariant: zero at launch entry
__device__ int   d_binstart[NBINS + 4];       // exclusive prefix (written by K2)
__device__ unsigned long long d_accum;        // invariant: zero at launch entry
__device__ int   d_done;                      // invariant: zero at launch entry

__device__ __forceinline__ int warp_iscan(int v) {
#pragma unroll
    for (int o = 1; o < 32; o <<= 1) {
        int n = __shfl_up_sync(0xffffffffu, v, o);
        if ((threadIdx.x & 31) >= o) v += n;
    }
    return v;
}

// ---------------------------------------------------------------------------
// K1: prep. g, loss, histogram atomic (returned old value == within-bin rank),
// packed (bin, rank) for the scatter in K2.
// ---------------------------------------------------------------------------
__global__ __launch_bounds__(TPB)
void k1_prep(const float* __restrict__ logits,
             const float* __restrict__ targets) {
    int i = blockIdx.x * TPB + threadIdx.x;
    float x  = logits[i];
    float tv = targets[i];
    float pred = 1.0f / (1.0f + __expf(-x));
    float g    = fabsf(pred - tv);
    d_g[i]    = g;
    d_loss[i] = fmaxf(x, 0.0f) - x * tv + log1pf(__expf(-fabsf(x)));
    int b    = min((int)(g * (float)NBINS), NBINS - 1);
    int rank = atomicAdd(&d_hist[b], 1);       // unique 0..cb-1 within bin
    d_pack[i] = (b << 14) | rank;              // b<4096 (12b), rank<16384 (14b)
}

// ---------------------------------------------------------------------------
// K2: per-CTA full exclusive prefix scan of d_hist in smem; scatter each
// owned element to its final contiguous position (single STG, no atomics).
// CTA 0 additionally publishes the prefix to d_binstart for K3.
// ---------------------------------------------------------------------------
__global__ __launch_bounds__(TPB)
void k2_scatter() {
    __shared__ int s_pref[NBINS + 4];
    __shared__ int s_wsum[4];
    const int t   = threadIdx.x;
    const int bid = blockIdx.x;
    const int i   = bid * TPB + t;

    // full exclusive prefix of d_hist
    {
        int h[BPT];
        const int4* hv = (const int4*)&d_hist[t * BPT];
#pragma unroll
        for (int q = 0; q < BPT / 4; q++) {             // 8 x LDG.128
            int4 a = hv[q];
            h[q * 4 + 0] = a.x; h[q * 4 + 1] = a.y;
            h[q * 4 + 2] = a.z; h[q * 4 + 3] = a.w;
        }
        int tot = 0;
#pragma unroll
        for (int k = 0; k < BPT; k++) tot += h[k];
        int incl = warp_iscan(tot);
        if ((t & 31) == 31) s_wsum[t >> 5] = incl;
        __syncthreads();
        if (t < 4) {
            int w = s_wsum[t];
#pragma unroll
            for (int o = 1; o < 4; o <<= 1) {
                int n = __shfl_up_sync(0xfu, w, o);
                if (t >= o) w += n;
            }
            s_wsum[t] = w;
        }
        __syncthreads();
        int base = incl - tot + ((t >> 5) ? s_wsum[(t >> 5) - 1] : 0);
#pragma unroll
        for (int k = 0; k < BPT; k++) {
            s_pref[t * BPT + k] = base;
            base += h[k];
        }
    }
    __syncthreads();

    // CTA 0 publishes the (identical-everywhere) prefix for K3
    if (bid == 0) {
#pragma unroll
        for (int q = 0; q < NBINS / 4 / TPB; q++)       // 8 x STG.128
            ((int4*)d_binstart)[q * TPB + t] = ((const int4*)s_pref)[q * TPB + t];
        if (t == 0) d_binstart[NBINS] = N_ELEMS;
    }

    // scatter owned element
    int pk   = d_pack[i];
    int b    = pk >> 14;
    int rank = pk & 0x3FFF;
    d_sorted[s_pref[b] + rank] = d_g[i];
}

// ---------------------------------------------------------------------------
// K3: load prefix + stage sorted array to smem; range-count query; weighted
// loss; deterministic u64 fixed-point finalize; last CTA restores hist=0.
// ---------------------------------------------------------------------------
__global__ __launch_bounds__(TPB)
void k3_query(float* __restrict__ out) {
    extern __shared__ char smem[];
    int*   s_pref   = (int*)smem;                       // NBINS+1 entries
    float* s_sorted = (float*)(smem + SMEM_SORT_OFF);   // N_ELEMS entries
    __shared__ unsigned long long s_acc[4];
    __shared__ int s_last;

    const int t   = threadIdx.x;
    const int bid = blockIdx.x;
    const int i   = bid * TPB + t;

    // load prefix (4 KB) and stage sorted array (64 KB), both coalesced
#pragma unroll
    for (int q = 0; q < NBINS / 4 / TPB; q++)           // 8 x LDG.128
        ((int4*)s_pref)[q * TPB + t] = ((const int4*)d_binstart)[q * TPB + t];
    if (t == 0) s_pref[NBINS] = N_ELEMS;
    {
        const float4* src = (const float4*)d_sorted;
        float4*       dst = (float4*)s_sorted;
#pragma unroll
        for (int k = 0; k < N_ELEMS / 4 / TPB; k++)     // 32 x LDG.128
            dst[k * TPB + t] = src[k * TPB + t];
    }
    float g    = d_g[i];
    float loss = d_loss[i];
    __syncthreads();

    // ---- range-count query ----
    // Interior bins [loBin+3, hiBin-3] guaranteed all-pass (>=1 bin-width
    // margin vs fp32 compare fuzz); bins outside [loBin-2, hiBin+2] guaranteed
    // all-fail; edge windows checked with the reference's exact fp32 compare.
    unsigned long long fixterm;
    {
        float p = g * (float)NBINS;
        int loBin = (int)floorf(p - 0.1f * (float)NBINS);
        int hiBin = (int)floorf(p + 0.1f * (float)NBINS);

        int iLo = min(max(loBin + 3, 0), NBINS);
        int iHi = min(max(hiBin - 2, 0), NBINS);
        int cnt = (iHi > iLo) ? (s_pref[iHi] - s_pref[iLo]) : 0;

        int a0 = max(loBin - 2, 0), b0 = min(loBin + 2, NBINS - 1);
        if (b0 >= a0) {
            int s = s_pref[a0], e = s_pref[b0 + 1];
#pragma unroll 8
            for (int idx = s; idx < e; idx++)
                cnt += (fabsf(s_sorted[idx] - g) <= DELTA_F) ? 1 : 0;
        }
        int a1 = max(hiBin - 2, 0), b1 = min(hiBin + 2, NBINS - 1);
        if (b1 >= a1) {
            int s = s_pref[a1], e = s_pref[b1 + 1];
#pragma unroll 8
            for (int idx = s; idx < e; idx++)
                cnt += (fabsf(s_sorted[idx] - g) <= DELTA_F) ? 1 : 0;
        }

        float GD   = (float)cnt / DELTA_F;
        float beta = (float)N_ELEMS / (GD + EPS_F);
        float term = beta * loss;      // >= 0
        fixterm = (unsigned long long)((double)term * FIX_SCALE);
    }

    // ---- deterministic finalize (u64 fixed-point; shuffle reduce) ----
    {
        unsigned long long v = fixterm;
#pragma unroll
        for (int off = 16; off > 0; off >>= 1)
            v += __shfl_down_sync(0xffffffffu, v, off);
        if ((t & 31) == 0) s_acc[t >> 5] = v;
        __syncthreads();
        if (t == 0) {
            unsigned long long w = s_acc[0] + s_acc[1] + s_acc[2] + s_acc[3];
            atomicAdd(&d_accum, w);
            __threadfence();
            int ticket = atomicAdd(&d_done, 1);
            if (ticket == NCTA - 1) {
                __threadfence();
                unsigned long long total = atomicAdd(&d_accum, 0ULL);
                out[0] = (float)(((double)total / FIX_SCALE) / (double)N_ELEMS);
                d_accum = 0ULL;        // restore invariants for next replay
                d_done  = 0;
                s_last  = 1;
                __threadfence();
            } else {
                s_last = 0;
            }
        }
        __syncthreads();
        // Last CTA restores hist=0 (K3 never reads d_hist -> race-free).
        if (s_last) {
            int4 z = make_int4(0, 0, 0, 0);
#pragma unroll
            for (int k = 0; k < NBINS / 4 / TPB; k++)   // 8 x STG.128
                ((int4*)d_hist)[k * TPB + t] = z;
        }
    }
}

// ---------------------------------------------------------------------------
extern "C" void kernel_launch(void* const* d_in, const int* in_sizes, int n_in,
                              void* d_out, int out_size) {
    const float* logits  = (const float*)d_in[0];
    const float* targets = (const float*)d_in[1];
    float* out = (float*)d_out;

    cudaFuncSetAttribute(k3_query, cudaFuncAttributeMaxDynamicSharedMemorySize,
                         SMEM_TOTAL_BYTES);

    k1_prep<<<NCTA, TPB>>>(logits, targets);
    k2_scatter<<<NCTA, TPB>>>();
    k3_query<<<NCTA, TPB, SMEM_TOTAL_BYTES>>>(out);
}